// round 1
// baseline (speedup 1.0000x reference)
#include <cuda_runtime.h>

#define Bn 64
#define Hn 512
#define Wn 512
#define HWn (Hn * Wn)

// Scratch: __device__ globals (no allocations allowed).
__device__ unsigned long long g_sum1[Bn];   // cup prob sum,  Q32 fixed point
__device__ unsigned long long g_sum2[Bn];   // disc prob sum, Q32 fixed point
__device__ int g_ymin1[Bn], g_ymax1[Bn];    // label 1 (cup) row extents
__device__ int g_ymin2[Bn], g_ymax2[Bn];    // label 2 (disc) row extents

__global__ void cdr_init_kernel() {
    int i = threadIdx.x;
    if (i < Bn) {
        g_sum1[i] = 0ULL; g_sum2[i] = 0ULL;
        g_ymin1[i] = Hn;  g_ymax1[i] = -1;
        g_ymin2[i] = Hn;  g_ymax2[i] = -1;
    }
}

// One block = one (batch, row-pair). 256 threads, each loads one float4 from
// each of the 3 channels (fully coalesced 16B accesses).
// grid.x = Bn * (Hn/2) = 64 * 256 = 16384 blocks.
__global__ void __launch_bounds__(256) cdr_main_kernel(const float* __restrict__ x) {
    const int b       = blockIdx.x >> 8;        // batch
    const int rowpair = blockIdx.x & 255;       // which pair of rows
    const int tid     = threadIdx.x;
    const int rsel    = tid >> 7;               // 0 or 1: which row of the pair
    const int row     = rowpair * 2 + rsel;
    const int c4      = tid & 127;              // float4 index within row (W/4=128)

    const float4* p = (const float4*)x;
    // float4-unit offsets; channel stride = HWn/4 float4s
    const size_t base = (((size_t)b * 3 * HWn + (size_t)row * Wn) >> 2) + (size_t)c4;
    float4 v0 = p[base];
    float4 v1 = p[base + (HWn >> 2)];
    float4 v2 = p[base + 2 * (HWn >> 2)];

    float s1 = 0.f, s2 = 0.f;
    bool any1 = false, any2 = false;

    const float* a0p = (const float*)&v0;
    const float* a1p = (const float*)&v1;
    const float* a2p = (const float*)&v2;

#pragma unroll
    for (int k = 0; k < 4; k++) {
        float a0 = a0p[k], a1 = a1p[k], a2 = a2p[k];

        // argmax with first-max tie semantics (strict compares)
        float m01 = a0; int lab = 0;
        if (a1 > a0)  { m01 = a1; lab = 1; }
        if (a2 > m01) { lab = 2; }
        any1 |= (lab == 1);
        any2 |= (lab == 2);

        // softmax p1, p2 with a1 as pivot: 2x EX2 + 1x RCP
        float e0 = __expf(a0 - a1);
        float e2 = __expf(a2 - a1);
        float inv = __fdividef(1.0f, e0 + 1.0f + e2);
        s1 += inv;        // p(channel 1) = cup
        s2 += e2 * inv;   // p(channel 2) = disc
    }

    // Deterministic warp reduction (fixed tree order)
#pragma unroll
    for (int o = 16; o > 0; o >>= 1) {
        s1 += __shfl_xor_sync(0xFFFFFFFFu, s1, o);
        s2 += __shfl_xor_sync(0xFFFFFFFFu, s2, o);
    }
    unsigned flags = (__any_sync(0xFFFFFFFFu, any1) ? 1u : 0u)
                   | (__any_sync(0xFFFFFFFFu, any2) ? 2u : 0u);

    __shared__ float    sh1[8], sh2[8];
    __shared__ unsigned shf[8];
    const int wid = tid >> 5, lid = tid & 31;
    if (lid == 0) { sh1[wid] = s1; sh2[wid] = s2; shf[wid] = flags; }
    __syncthreads();

    if (tid == 0) {
        float bs1 = 0.f, bs2 = 0.f;
#pragma unroll
        for (int w = 0; w < 8; w++) { bs1 += sh1[w]; bs2 += sh2[w]; }
        // Fixed-point commit: integer atomics commute -> deterministic result.
        atomicAdd(&g_sum1[b], (unsigned long long)((double)bs1 * 4294967296.0));
        atomicAdd(&g_sum2[b], (unsigned long long)((double)bs2 * 4294967296.0));

        unsigned f0 = shf[0] | shf[1] | shf[2] | shf[3];   // row (rowpair*2)
        unsigned f1 = shf[4] | shf[5] | shf[6] | shf[7];   // row (rowpair*2+1)
        int r0 = rowpair * 2, r1 = r0 + 1;
        if (f0 & 1u) { atomicMin(&g_ymin1[b], r0); atomicMax(&g_ymax1[b], r0); }
        if (f0 & 2u) { atomicMin(&g_ymin2[b], r0); atomicMax(&g_ymax2[b], r0); }
        if (f1 & 1u) { atomicMin(&g_ymin1[b], r1); atomicMax(&g_ymax1[b], r1); }
        if (f1 & 2u) { atomicMin(&g_ymin2[b], r1); atomicMax(&g_ymax2[b], r1); }
    }
}

__global__ void cdr_final_kernel(float* __restrict__ out) {
    int b = threadIdx.x;
    if (b < Bn) {
        float h1 = (g_ymax1[b] >= 0) ? (float)(g_ymax1[b] - g_ymin1[b]) : 0.0f; // cup
        float h2 = (g_ymax2[b] >= 0) ? (float)(g_ymax2[b] - g_ymin2[b]) : 0.0f; // disc
        float cdr = h1 / (h2 + 1e-6f);
        const double inv = 1.0 / (4294967296.0 * (double)HWn);
        float cup_mean  = (float)((double)g_sum1[b] * inv);
        float disc_mean = (float)((double)g_sum2[b] * inv);
        out[b * 5 + 0] = cdr;
        out[b * 5 + 1] = disc_mean;
        out[b * 5 + 2] = cup_mean;
        out[b * 5 + 3] = disc_mean;
        out[b * 5 + 4] = cup_mean;
    }
}

extern "C" void kernel_launch(void* const* d_in, const int* in_sizes, int n_in,
                              void* d_out, int out_size) {
    const float* x = (const float*)d_in[0];
    float* out = (float*)d_out;
    (void)in_sizes; (void)n_in; (void)out_size;

    cdr_init_kernel<<<1, 64>>>();
    cdr_main_kernel<<<Bn * (Hn / 2), 256>>>(x);
    cdr_final_kernel<<<1, 64>>>(out);
}

// round 2
// speedup vs baseline: 1.6788x; 1.6788x over previous
#include <cuda_runtime.h>
#include <climits>

#define Bn 64
#define Hn 512
#define Wn 512
#define HWn (Hn * Wn)
#define HW4 (HWn / 4)
#define BLOCKS_PER_BATCH 128          // 4 rows per block
#define GRID (Bn * BLOCKS_PER_BATCH)  // 8192

// Per-block partials — fully overwritten every launch before being read,
// so no init kernel is needed. Counter is self-resetting (last block zeroes it).
__device__ float    g_ps1[GRID];
__device__ float    g_ps2[GRID];
__device__ unsigned g_pflags[GRID];
__device__ unsigned g_count[Bn];      // zero at module load; reset each launch

__global__ void __launch_bounds__(256) cdr_fused_kernel(const float* __restrict__ x,
                                                        float* __restrict__ out) {
    const int b    = blockIdx.x >> 7;       // batch
    const int quad = blockIdx.x & 127;      // which group of 4 rows
    const int tid  = threadIdx.x;
    const int rsel = tid >> 6;              // 0..3: row within quad
    const int c4   = tid & 63;              // float4 index in first half of row
    const int row  = quad * 4 + rsel;

    // ---- Phase 1: streaming load + per-pixel math ----
    const float4* p = (const float4*)x;
    const size_t base4 = (((size_t)b * 3 * HWn + (size_t)row * Wn) >> 2) + (size_t)c4;
    // 6 front-batched 16B loads (MLP_p1 = 6), fully coalesced
    float4 v0a = p[base4];
    float4 v1a = p[base4 + HW4];
    float4 v2a = p[base4 + 2 * HW4];
    float4 v0b = p[base4 + 64];
    float4 v1b = p[base4 + HW4 + 64];
    float4 v2b = p[base4 + 2 * HW4 + 64];

    float s1 = 0.f, s2 = 0.f;
    bool any1 = false, any2 = false;

    const float* f0 = (const float*)&v0a;
    const float* f1 = (const float*)&v1a;
    const float* f2 = (const float*)&v2a;
    const float* h0 = (const float*)&v0b;
    const float* h1 = (const float*)&v1b;
    const float* h2 = (const float*)&v2b;

#pragma unroll
    for (int k = 0; k < 8; k++) {
        float a0 = (k < 4) ? f0[k] : h0[k - 4];
        float a1 = (k < 4) ? f1[k] : h1[k - 4];
        float a2 = (k < 4) ? f2[k] : h2[k - 4];

        // argmax, first-occurrence tie semantics (strict >)
        float m01 = fmaxf(a0, a1);
        bool  l1  = a1 > a0;
        bool  l2  = a2 > m01;
        any1 |= (l1 && !l2);
        any2 |= l2;

        // softmax p1,p2 pivoted on a1: 2x EX2 + 1x RCP
        float e0  = __expf(a0 - a1);
        float e2  = __expf(a2 - a1);
        float inv = __fdividef(1.0f, e0 + 1.0f + e2);
        s1 += inv;        // p(channel 1) = cup
        s2 += e2 * inv;   // p(channel 2) = disc
    }

    // ---- Phase 2: deterministic in-block reduction ----
#pragma unroll
    for (int o = 16; o > 0; o >>= 1) {
        s1 += __shfl_xor_sync(0xFFFFFFFFu, s1, o);
        s2 += __shfl_xor_sync(0xFFFFFFFFu, s2, o);
    }
    unsigned wflags = (__any_sync(0xFFFFFFFFu, any1) ? 1u : 0u)
                    | (__any_sync(0xFFFFFFFFu, any2) ? 2u : 0u);

    __shared__ float    sw1[8], sw2[8];
    __shared__ unsigned swf[8];
    const int wid = tid >> 5, lid = tid & 31;
    if (lid == 0) { sw1[wid] = s1; sw2[wid] = s2; swf[wid] = wflags; }
    __syncthreads();

    if (tid == 0) {
        float bs1 = 0.f, bs2 = 0.f;
        unsigned fw = 0;
#pragma unroll
        for (int w = 0; w < 8; w++) { bs1 += sw1[w]; bs2 += sw2[w]; }
#pragma unroll
        for (int r = 0; r < 4; r++) {
            unsigned f = swf[2 * r] | swf[2 * r + 1];  // 2 warps per row
            fw |= f << (2 * r);                        // bit 2r: label1, 2r+1: label2
        }
        g_ps1[blockIdx.x]    = bs1;
        g_ps2[blockIdx.x]    = bs2;
        g_pflags[blockIdx.x] = fw;
    }

    // ---- Phase 3: last block of each batch finalizes ----
    __shared__ int lastFlag;
    if (tid == 0) {
        __threadfence();
        lastFlag = (atomicAdd(&g_count[b], 1u) == BLOCKS_PER_BATCH - 1);
    }
    __syncthreads();
    if (!lastFlag) return;

    float    v1 = 0.f, v2 = 0.f;
    int      mn1 = INT_MAX, mx1 = -1, mn2 = INT_MAX, mx2 = -1;
    if (tid < BLOCKS_PER_BATCH) {
        int idx = b * BLOCKS_PER_BATCH + tid;
        v1 = g_ps1[idx];
        v2 = g_ps2[idx];
        unsigned fl = g_pflags[idx];
#pragma unroll
        for (int r = 0; r < 4; r++) {
            int rr = tid * 4 + r;
            if (fl & (1u << (2 * r)))     { mn1 = min(mn1, rr); mx1 = max(mx1, rr); }
            if (fl & (1u << (2 * r + 1))) { mn2 = min(mn2, rr); mx2 = max(mx2, rr); }
        }
    }

    __shared__ float ra[256], rb[256];
    __shared__ int   ja[256], jb[256], jc[256], jd[256];
    ra[tid] = v1;  rb[tid] = v2;
    ja[tid] = mn1; jb[tid] = mx1; jc[tid] = mn2; jd[tid] = mx2;
    __syncthreads();
#pragma unroll
    for (int s = 128; s > 0; s >>= 1) {
        if (tid < s) {
            ra[tid] += ra[tid + s];
            rb[tid] += rb[tid + s];
            ja[tid] = min(ja[tid], ja[tid + s]);
            jb[tid] = max(jb[tid], jb[tid + s]);
            jc[tid] = min(jc[tid], jc[tid + s]);
            jd[tid] = max(jd[tid], jd[tid + s]);
        }
        __syncthreads();
    }

    if (tid == 0) {
        const float inv_hw = 1.0f / (float)HWn;
        float cup_mean  = ra[0] * inv_hw;
        float disc_mean = rb[0] * inv_hw;
        float hcup  = (jb[0] >= 0) ? (float)(jb[0] - ja[0]) : 0.0f;
        float hdisc = (jd[0] >= 0) ? (float)(jd[0] - jc[0]) : 0.0f;
        float cdr = hcup / (hdisc + 1e-6f);
        out[b * 5 + 0] = cdr;
        out[b * 5 + 1] = disc_mean;
        out[b * 5 + 2] = cup_mean;
        out[b * 5 + 3] = disc_mean;
        out[b * 5 + 4] = cup_mean;
        g_count[b] = 0;   // self-reset: deterministic across graph replays
    }
}

extern "C" void kernel_launch(void* const* d_in, const int* in_sizes, int n_in,
                              void* d_out, int out_size) {
    const float* x = (const float*)d_in[0];
    float* out = (float*)d_out;
    (void)in_sizes; (void)n_in; (void)out_size;

    cdr_fused_kernel<<<GRID, 256>>>(x, out);
}